// round 9
// baseline (speedup 1.0000x reference)
#include <cuda_runtime.h>
#include <cuda_fp16.h>
#include <cuda_bf16.h>
#include <cstdint>

// VectorQuantizer: N=65536 rows, D=256, K=1024 codes.
// Pass 1: fp16 mma.sync m16n8k16 GEMM-argmin (512 thr, warp tile 64x32, acc=64 regs,
//   ldmatrix A, fragment-prepacked B from GMEM, double-buffered). margin<0.15 -> flag.
// fix32: fp32 recompute of flagged rows; margin < 1e-3 -> fix64.
// fix64: exact fp64 (8-chain ILP) + TIE_EPS=7.5e-5 window pick-lowest (R6-calibrated).

#define N_ROWS   65536
#define DIM      256
#define K_CODES  1024
#define FLAG_THR 0.15f
#define TIE_EPS  7.5e-5
#define AMB_CAP  16384
#define AMB2_CAP 4096
#define A_S      264          // A smem stride in halves

__device__ double   g_loss_acc;
__device__ float    g_enorm[K_CODES];
__device__ double   g_enorm_d[K_CODES];
__device__ float    g_eT[K_CODES * DIM];      // e transposed [k][d]
__device__ uint32_t g_bpk[4 * 8 * 2 * 256 * 8]; // fp16 B fragments: [st][kc][s][code][8w]
__device__ int      g_idx[N_ROWS];
__device__ int      g_amb[AMB_CAP];
__device__ int      g_amb_count;
__device__ int      g_amb2[AMB2_CAP];
__device__ int      g_amb2_count;

// smem byte offsets
#define OFF_A    0                       // 128 x 264 halves = 67584 B
#define OFF_BP   67584                   // 2 buf x 2 ks x 256 code x 10 words = 40960 B
#define OFF_REDB 108544                  // 1024 f
#define OFF_REDS 112640                  // 1024 f
#define OFF_REDI 116736                  // 1024 i
#define OFF_BROW 120832                  // 128 f
#define OFF_SROW 121344                  // 128 f
#define OFF_IROW 121856                  // 128 i
#define OFF_SEN  122368                  // 256 f
#define OFF_LRED 123392                  // 16 f
#define SMEM_BYTES 123456

__device__ __forceinline__ uint32_t smem_u32(const void* p) {
    uint32_t a;
    asm("{ .reg .u64 t; cvta.to.shared.u64 t, %1; cvt.u32.u64 %0, t; }" : "=r"(a) : "l"(p));
    return a;
}
__device__ __forceinline__ uint32_t packh2(float lo, float hi) {
    __half2 h = __floats2half2_rn(lo, hi);
    return *(uint32_t*)&h;
}
__device__ __forceinline__ void mma_f16(float c[4], const uint32_t a[4],
                                        uint32_t b0, uint32_t b1) {
    asm volatile(
        "mma.sync.aligned.m16n8k16.row.col.f32.f16.f16.f32 "
        "{%0,%1,%2,%3}, {%4,%5,%6,%7}, {%8,%9}, {%0,%1,%2,%3};"
        : "+f"(c[0]), "+f"(c[1]), "+f"(c[2]), "+f"(c[3])
        : "r"(a[0]), "r"(a[1]), "r"(a[2]), "r"(a[3]), "r"(b0), "r"(b1));
}

// ---------------------------------------------------------------------------
// prep: blocks 0-255 transpose eT; 256-259 enorms + zero; 260-291 pack B frags.
__global__ void vq_prep(const float* __restrict__ e) {
    int b = blockIdx.x;
    if (b < 256) {
        int d = b;
        for (int k = threadIdx.x; k < K_CODES; k += 256)
            g_eT[k * DIM + d] = e[d * K_CODES + k];
    } else if (b < 260) {
        int k = (b - 256) * 256 + threadIdx.x;
        double s = 0.0;
        for (int d = 0; d < DIM; d++) {
            double v = (double)e[d * K_CODES + k];
            s += v * v;
        }
        g_enorm[k]   = (float)s;
        g_enorm_d[k] = s;
        if (b == 256 && threadIdx.x == 0) {
            g_loss_acc = 0.0; g_amb_count = 0; g_amb2_count = 0;
        }
    } else {
        // pack: linear over (kc 0..7) x (k 0..1023); consecutive tid -> consecutive k
        int linear = (b - 260) * 256 + threadIdx.x;   // 0..8191
        int kc = linear >> 10;
        int k  = linear & 1023;
        int st = k >> 8, c = k & 255;
        #pragma unroll
        for (int s = 0; s < 2; s++) {
            int dbase = kc * 32 + s * 16;
            uint32_t w[8];
            #pragma unroll
            for (int t = 0; t < 4; t++) {
                w[2*t]   = packh2(e[(size_t)(dbase + 2*t)     * K_CODES + k],
                                  e[(size_t)(dbase + 2*t + 1) * K_CODES + k]);
                w[2*t+1] = packh2(e[(size_t)(dbase + 8 + 2*t)     * K_CODES + k],
                                  e[(size_t)(dbase + 8 + 2*t + 1) * K_CODES + k]);
            }
            uint32_t* dst = g_bpk + (size_t)(((st * 8 + kc) * 2 + s) * 256 + c) * 8;
            #pragma unroll
            for (int j = 0; j < 8; j++) dst[j] = w[j];
        }
    }
}

// ---------------------------------------------------------------------------
__global__ void __launch_bounds__(512) vq_mma(const float* __restrict__ x,
                                              float* __restrict__ out) {
    extern __shared__ char sm[];
    __half*   As   = (__half*)(sm + OFF_A);
    uint32_t* bpw  = (uint32_t*)(sm + OFF_BP);
    float*    redb = (float*)(sm + OFF_REDB);
    float*    reds = (float*)(sm + OFF_REDS);
    int*      redi = (int*)(sm + OFF_REDI);
    float*    brow = (float*)(sm + OFF_BROW);
    float*    srow = (float*)(sm + OFF_SROW);
    int*      irow = (int*)(sm + OFF_IROW);
    float*    sen  = (float*)(sm + OFF_SEN);
    float*    lred = (float*)(sm + OFF_LRED);

    const int tid  = threadIdx.x;
    const int lane = tid & 31;
    const int wid  = tid >> 5;
    const int g = lane >> 2;
    const int t = lane & 3;
    const int rowGroup = wid >> 3;   // 0..1
    const int codeCol  = wid & 7;    // 0..7
    const int row0 = blockIdx.x * 128;
    const float* xblk = x + (size_t)row0 * DIM;
    const uint32_t sbA = smem_u32(As);

    // ---- stage A (fp16) ----
    #pragma unroll
    for (int it = 0; it < 16; it++) {
        int i  = it * 512 + tid;
        int r  = i >> 6;
        int c4 = i & 63;
        float4 v = ((const float4*)(xblk + (size_t)r * DIM))[c4];
        __half2* dst = (__half2*)&As[r * A_S + c4 * 4];
        dst[0] = __floats2half2_rn(v.x, v.y);
        dst[1] = __floats2half2_rn(v.z, v.w);
    }
    if (tid < 128) { brow[tid] = 3.4e38f; srow[tid] = 3.4e38f; irow[tid] = 0; }

    // per-thread ldmatrix base addresses per mt
    const int lr = lane & 7, bq = lane >> 3;
    uint32_t aaddr[4];
    #pragma unroll
    for (int mt = 0; mt < 4; mt++) {
        int row = rowGroup * 64 + mt * 16 + (bq & 1) * 8 + lr;
        aaddr[mt] = sbA + (uint32_t)(row * A_S + (bq >> 1) * 8) * 2;
    }

    for (int st = 0; st < 4; st++) {
        // stage chunk 0 into buf 0
        {
            int s = tid >> 8, c = tid & 255;
            const uint4* src = (const uint4*)(g_bpk +
                (size_t)(((st * 8 + 0) * 2 + s) * 256 + c) * 8);
            uint4 v0 = src[0], v1 = src[1];
            uint2* d2 = (uint2*)&bpw[s * 2560 + c * 10];
            d2[0] = make_uint2(v0.x, v0.y); d2[1] = make_uint2(v0.z, v0.w);
            d2[2] = make_uint2(v1.x, v1.y); d2[3] = make_uint2(v1.z, v1.w);
        }
        if (tid < 256) sen[tid] = g_enorm[st * 256 + tid];
        __syncthreads();

        float acc[4][4][4];
        #pragma unroll
        for (int mt = 0; mt < 4; mt++)
            #pragma unroll
            for (int nt = 0; nt < 4; nt++)
                #pragma unroll
                for (int q = 0; q < 4; q++) acc[mt][nt][q] = 0.f;

        for (int kc = 0; kc < 8; kc++) {
            int buf = kc & 1;
            if (kc + 1 < 8) {   // prefetch next chunk into other buffer
                int s = tid >> 8, c = tid & 255;
                const uint4* src = (const uint4*)(g_bpk +
                    (size_t)(((st * 8 + kc + 1) * 2 + s) * 256 + c) * 8);
                uint4 v0 = src[0], v1 = src[1];
                uint2* d2 = (uint2*)&bpw[(buf ^ 1) * 5120 + s * 2560 + c * 10];
                d2[0] = make_uint2(v0.x, v0.y); d2[1] = make_uint2(v0.z, v0.w);
                d2[2] = make_uint2(v1.x, v1.y); d2[3] = make_uint2(v1.z, v1.w);
            }
            #pragma unroll
            for (int ks2 = 0; ks2 < 2; ks2++) {
                int kglob = kc * 32 + ks2 * 16;
                uint32_t a[4][4];
                #pragma unroll
                for (int mt = 0; mt < 4; mt++)
                    asm volatile(
                        "ldmatrix.sync.aligned.m8n8.x4.shared.b16 {%0,%1,%2,%3}, [%4];"
                        : "=r"(a[mt][0]), "=r"(a[mt][1]), "=r"(a[mt][2]), "=r"(a[mt][3])
                        : "r"(aaddr[mt] + (uint32_t)kglob * 2));
                #pragma unroll
                for (int nt = 0; nt < 4; nt++) {
                    int cl = codeCol * 32 + nt * 8 + g;
                    uint2 bb = *(const uint2*)&bpw[buf * 5120 + ks2 * 2560 + cl * 10 + 2 * t];
                    #pragma unroll
                    for (int mt = 0; mt < 4; mt++)
                        mma_f16(acc[mt][nt], a[mt], bb.x, bb.y);
                }
            }
            __syncthreads();
        }

        // ---- supertile epilogue ----
        float rb[8], rs[8]; int rix[8];
        #pragma unroll
        for (int s2 = 0; s2 < 8; s2++) { rb[s2] = 3.4e38f; rs[s2] = 3.4e38f; rix[s2] = 0; }

        #pragma unroll
        for (int mt = 0; mt < 4; mt++) {
            #pragma unroll
            for (int nt = 0; nt < 4; nt++) {
                int cl0 = codeCol * 32 + nt * 8 + 2 * t;
                float n0 = sen[cl0], n1 = sen[cl0 + 1];
                #pragma unroll
                for (int h = 0; h < 2; h++) {
                    int slot = mt * 2 + h;
                    float d0 = fmaf(-2.f, acc[mt][nt][2 * h],     n0);
                    float d1 = fmaf(-2.f, acc[mt][nt][2 * h + 1], n1);
                    if (d0 < rb[slot]) { rs[slot] = rb[slot]; rb[slot] = d0; rix[slot] = cl0; }
                    else if (d0 < rs[slot]) rs[slot] = d0;
                    if (d1 < rb[slot]) { rs[slot] = rb[slot]; rb[slot] = d1; rix[slot] = cl0 + 1; }
                    else if (d1 < rs[slot]) rs[slot] = d1;
                }
            }
        }
        #pragma unroll
        for (int off = 1; off <= 2; off <<= 1) {
            #pragma unroll
            for (int s2 = 0; s2 < 8; s2++) {
                float ob = __shfl_xor_sync(0xffffffffu, rb[s2], off);
                float os = __shfl_xor_sync(0xffffffffu, rs[s2], off);
                int   oi = __shfl_xor_sync(0xffffffffu, rix[s2], off);
                if (ob < rb[s2]) { rs[s2] = fminf(rb[s2], os); rb[s2] = ob; rix[s2] = oi; }
                else             { rs[s2] = fminf(rs[s2], ob); }
            }
        }
        if (t == 0) {
            #pragma unroll
            for (int s2 = 0; s2 < 8; s2++) {
                int mt = s2 >> 1, h = s2 & 1;
                int row = rowGroup * 64 + mt * 16 + g + h * 8;
                redb[row * 8 + codeCol] = rb[s2];
                reds[row * 8 + codeCol] = rs[s2];
                redi[row * 8 + codeCol] = st * 256 + rix[s2];
            }
        }
        __syncthreads();
        if (tid < 128) {
            float b = brow[tid], s = srow[tid]; int i = irow[tid];
            #pragma unroll
            for (int c = 0; c < 8; c++) {
                float ob = redb[tid * 8 + c], os = reds[tid * 8 + c];
                int   oi = redi[tid * 8 + c];
                if (ob < b) { s = fminf(b, os); b = ob; i = oi; }
                else        { s = fminf(s, ob); }
            }
            brow[tid] = b; srow[tid] = s; irow[tid] = i;
        }
        __syncthreads();
    }

    // ---- flag + g_idx ----
    if (tid < 128) {
        int grow = row0 + tid;
        g_idx[grow] = irow[tid];
        if (srow[tid] - brow[tid] < FLAG_THR) {
            int slot = atomicAdd(&g_amb_count, 1);
            if (slot < AMB_CAP) g_amb[slot] = grow;
        }
    }
    __syncthreads();

    // ---- gather + straight-through output + loss (original fp32) ----
    float local = 0.f;
    #pragma unroll
    for (int rr = 0; rr < 8; rr++) {
        int row = wid * 8 + rr;
        int idx = irow[row];
        const float* esrc = g_eT + (size_t)idx * DIM;
        const float* xrow = xblk + (size_t)row * DIM;
        float* orow = out + (size_t)(row0 + row) * DIM;
        #pragma unroll
        for (int kk = 0; kk < 8; kk++) {
            int d = kk * 32 + lane;
            float q  = esrc[d];
            float xv = xrow[d];
            float dq = q - xv;
            local += dq * dq;
            orow[d] = xv + dq;
        }
    }
    #pragma unroll
    for (int off = 16; off; off >>= 1)
        local += __shfl_xor_sync(0xffffffffu, local, off);
    if (lane == 0) lred[wid] = local;
    __syncthreads();
    if (tid == 0) {
        float ssum = 0.f;
        #pragma unroll
        for (int w = 0; w < 16; w++) ssum += lred[w];
        atomicAdd(&g_loss_acc, (double)ssum);
    }
}

// ---------------------------------------------------------------------------
// fix32: fp32 recompute of flagged rows. margin<1e-3 -> fix64, else patch.
__global__ void vq_fix32(const float* __restrict__ x, float* __restrict__ out) {
    __shared__ float  xr[DIM];
    __shared__ float  rb[256], rs[256];
    __shared__ int    rix[256];
    __shared__ double sdd[256];

    const int tid = threadIdx.x;
    int total = g_amb_count; if (total > AMB_CAP) total = AMB_CAP;

    for (int it = blockIdx.x; it < total; it += gridDim.x) {
        int row = g_amb[it];
        xr[tid] = x[(size_t)row * DIM + tid];
        __syncthreads();

        float s0 = 0.f, s1 = 0.f, s2 = 0.f, s3 = 0.f;
        const float* eb = g_eT + (size_t)tid * 4 * DIM;
        #pragma unroll 4
        for (int d = 0; d < DIM; d++) {
            float xv = xr[d];
            s0 = fmaf(xv, eb[d], s0);
            s1 = fmaf(xv, eb[DIM + d], s1);
            s2 = fmaf(xv, eb[2 * DIM + d], s2);
            s3 = fmaf(xv, eb[3 * DIM + d], s3);
        }
        float dj[4];
        dj[0] = fmaf(-2.f, s0, g_enorm[tid * 4 + 0]);
        dj[1] = fmaf(-2.f, s1, g_enorm[tid * 4 + 1]);
        dj[2] = fmaf(-2.f, s2, g_enorm[tid * 4 + 2]);
        dj[3] = fmaf(-2.f, s3, g_enorm[tid * 4 + 3]);

        float b = 3.4e38f, s = 3.4e38f; int bi = 0;
        #pragma unroll
        for (int j = 0; j < 4; j++) {
            int k = tid * 4 + j;
            if (dj[j] < b) { s = b; b = dj[j]; bi = k; }
            else if (dj[j] < s) s = dj[j];
        }
        rb[tid] = b; rs[tid] = s; rix[tid] = bi;
        __syncthreads();
        for (int off = 128; off; off >>= 1) {
            if (tid < off) {
                float b2 = rb[tid + off], s2v = rs[tid + off];
                int   i2 = rix[tid + off];
                float b1 = rb[tid], s1v = rs[tid];
                int   i1 = rix[tid];
                if (b2 < b1 || (b2 == b1 && i2 < i1)) {
                    rb[tid] = b2; rix[tid] = i2; rs[tid] = fminf(b1, s2v);
                } else {
                    rs[tid] = fminf(s1v, b2);
                }
            }
            __syncthreads();
        }
        float margin = rs[0] - rb[0];
        int newIdx = rix[0];
        int oldIdx = g_idx[row];
        __syncthreads();

        if (margin < 1e-3f) {
            if (tid == 0) {
                int slot = atomicAdd(&g_amb2_count, 1);
                if (slot < AMB2_CAP) g_amb2[slot] = row;
            }
        } else if (newIdx != oldIdx) {
            float xv = xr[tid];
            float qn = g_eT[(size_t)newIdx * DIM + tid];
            float qo = g_eT[(size_t)oldIdx * DIM + tid];
            out[(size_t)row * DIM + tid] = xv + (qn - xv);
            if (tid == 0) g_idx[row] = newIdx;
            double dn = (double)(qn - xv), dl = (double)(qo - xv);
            sdd[tid] = dn * dn - dl * dl;
            __syncthreads();
            for (int off = 128; off; off >>= 1) {
                if (tid < off) sdd[tid] += sdd[tid + off];
                __syncthreads();
            }
            if (tid == 0) atomicAdd(&g_loss_acc, sdd[0]);
        }
        __syncthreads();
    }
}

// ---------------------------------------------------------------------------
// fix64: exact fp64 (8-chain ILP) + TIE_EPS window, pick lowest (R6-calibrated).
__global__ void vq_fix64(const float* __restrict__ x, float* __restrict__ out) {
    __shared__ float  xr[DIM];
    __shared__ double sdd[256];
    __shared__ double svv[256];
    __shared__ int    sii[256];
    __shared__ double s_minv;

    const int tid = threadIdx.x;
    int total = g_amb2_count; if (total > AMB2_CAP) total = AMB2_CAP;

    for (int it = blockIdx.x; it < total; it += gridDim.x) {
        int row = g_amb2[it];
        xr[tid] = x[(size_t)row * DIM + tid];
        __syncthreads();

        sdd[tid] = (double)xr[tid] * (double)xr[tid];
        __syncthreads();
        for (int off = 128; off; off >>= 1) {
            if (tid < off) sdd[tid] += sdd[tid + off];
            __syncthreads();
        }
        double xn = sdd[0];
        __syncthreads();

        // 4 codes/thread, each with lo/hi dim chains (8 independent chains)
        double sa[4] = {0, 0, 0, 0}, sb[4] = {0, 0, 0, 0};
        const float* eb = g_eT + (size_t)tid * 4 * DIM;
        for (int d = 0; d < 128; d++) {
            double x0 = (double)xr[d], x1 = (double)xr[d + 128];
            #pragma unroll
            for (int j = 0; j < 4; j++) {
                sa[j] += x0 * (double)eb[j * DIM + d];
                sb[j] += x1 * (double)eb[j * DIM + 128 + d];
            }
        }
        double dist[4];
        #pragma unroll
        for (int j = 0; j < 4; j++)
            dist[j] = xn + g_enorm_d[tid * 4 + j] - 2.0 * (sa[j] + sb[j]);

        double bv = 1e300; int bi = 0x7fffffff;
        #pragma unroll
        for (int j = 0; j < 4; j++) {
            int k = tid * 4 + j;
            if (dist[j] < bv || (dist[j] == bv && k < bi)) { bv = dist[j]; bi = k; }
        }
        svv[tid] = bv; sii[tid] = bi;
        __syncthreads();
        for (int off = 128; off; off >>= 1) {
            if (tid < off) {
                double v2 = svv[tid + off]; int i2 = sii[tid + off];
                if (v2 < svv[tid] || (v2 == svv[tid] && i2 < sii[tid])) {
                    svv[tid] = v2; sii[tid] = i2;
                }
            }
            __syncthreads();
        }
        if (tid == 0) s_minv = svv[0];
        __syncthreads();
        double minv = s_minv;

        int cand = 0x7fffffff;
        #pragma unroll
        for (int j = 0; j < 4; j++) {
            int k = tid * 4 + j;
            if (dist[j] <= minv + TIE_EPS && k < cand) cand = k;
        }
        sii[tid] = cand;
        __syncthreads();
        for (int off = 128; off; off >>= 1) {
            if (tid < off) { if (sii[tid + off] < sii[tid]) sii[tid] = sii[tid + off]; }
            __syncthreads();
        }
        int newIdx = sii[0];
        int oldIdx = g_idx[row];
        __syncthreads();

        if (newIdx != oldIdx) {
            float xv = xr[tid];
            float qn = g_eT[(size_t)newIdx * DIM + tid];
            float qo = g_eT[(size_t)oldIdx * DIM + tid];
            out[(size_t)row * DIM + tid] = xv + (qn - xv);
            double dn = (double)(qn - xv), dl = (double)(qo - xv);
            sdd[tid] = dn * dn - dl * dl;
            __syncthreads();
            for (int off = 128; off; off >>= 1) {
                if (tid < off) sdd[tid] += sdd[tid + off];
                __syncthreads();
            }
            if (tid == 0) atomicAdd(&g_loss_acc, sdd[0]);
        }
        __syncthreads();
    }
}

// ---------------------------------------------------------------------------
__global__ void vq_finish(float* __restrict__ out) {
    const double nd = (double)N_ROWS * (double)DIM;
    out[(size_t)N_ROWS * DIM] = (float)(1.25 * g_loss_acc / nd);
}

// ---------------------------------------------------------------------------
extern "C" void kernel_launch(void* const* d_in, const int* in_sizes, int n_in,
                              void* d_out, int out_size) {
    const float* x = (const float*)d_in[0];
    const float* e = (const float*)d_in[1];
    if (n_in >= 2 && in_sizes[0] == K_CODES * DIM && in_sizes[1] == N_ROWS * DIM) {
        e = (const float*)d_in[0];
        x = (const float*)d_in[1];
    }
    float* out = (float*)d_out;

    cudaFuncSetAttribute(vq_mma, cudaFuncAttributeMaxDynamicSharedMemorySize, SMEM_BYTES);

    vq_prep<<<292, 256>>>(e);
    vq_mma<<<N_ROWS / 128, 512, SMEM_BYTES>>>(x, out);
    vq_fix32<<<1024, 256>>>(x, out);
    vq_fix64<<<128, 256>>>(x, out);
    if (out_size > N_ROWS * DIM) vq_finish<<<1, 1>>>(out);
}